// round 2
// baseline (speedup 1.0000x reference)
#include <cuda_runtime.h>

#define BB 64
#define TT 2048
#define ED 512
#define DD 1024
#define AD 128
#define NF 32
#define KS 31
#define PADW 15

// scratch (no allocations allowed)
__device__ float g_M[AD * KS];        // folded conv*W_location  [a][k]
__device__ float g_dp[BB * AD];       // decoder projection      [b][a]
__device__ float g_energy[BB * TT];   // pre-softmax energies

// ---------------------------------------------------------------------------
// Fold conv_w [F,1,KS] into W_location [A,F]:  M[a][k] = sum_f Wloc[a,f]*cw[f,k]
__global__ void k_prep_M(const float* __restrict__ Wloc,
                         const float* __restrict__ convw) {
    int idx = blockIdx.x * blockDim.x + threadIdx.x;
    if (idx < AD * KS) {
        int a = idx / KS, k = idx % KS;
        float s = 0.f;
#pragma unroll
        for (int f = 0; f < NF; ++f) s += Wloc[a * NF + f] * convw[f * KS + k];
        g_M[idx] = s;
    }
}

// ---------------------------------------------------------------------------
// dec_proj[b][a] = W_decoder[a,:] . decoder_state[b,:]
__global__ void k_decproj(const float* __restrict__ Wdec,
                          const float* __restrict__ dec) {
    int b = blockIdx.x;
    int a = threadIdx.x;
    const float* w = Wdec + a * DD;
    const float* x = dec + b * DD;
    float s = 0.f;
#pragma unroll 8
    for (int d = 0; d < DD; ++d) s += w[d] * x[d];
    g_dp[b * AD + a] = s;
}

// ---------------------------------------------------------------------------
__global__ void k_zero(float* __restrict__ out) {
    out[blockIdx.x * blockDim.x + threadIdx.x] = 0.f;
}

// ---------------------------------------------------------------------------
// Energy kernel: per block, 128 t-rows x 128 a-cols of enc_proj GEMM,
// plus folded location conv, then epilogue energy[t] = sum_a v[a]*tanh(...).
// Block: 256 threads = 16(tx: a-groups) x 16(ty: t-groups); 8x8 register tile.
__global__ __launch_bounds__(256) void k_energy(
    const float* __restrict__ enc, const float* __restrict__ Wenc,
    const float* __restrict__ prev, const int* __restrict__ mask,
    const float* __restrict__ v) {
    __shared__ __align__(16) float Es[128 * 33];   // [t][k] pad 33
    __shared__ __align__(16) float WsT[32 * 136];  // [k][a] pad 136 (also reused for M^T)
    __shared__ float prev_s[160];
    __shared__ float dps[AD];
    __shared__ float vs[AD];

    const int tid = threadIdx.x;
    const int tx = tid & 15;         // a-group
    const int ty = tid >> 4;         // t-group
    const int b = blockIdx.y;
    const int t0 = blockIdx.x * 128;

    if (tid < AD) { dps[tid] = g_dp[b * AD + tid]; vs[tid] = v[tid]; }
    for (int i = tid; i < 158; i += 256) {
        int tg = t0 - PADW + i;
        prev_s[i] = (tg >= 0 && tg < TT) ? prev[b * TT + tg] : 0.f;
    }

    float acc[8][8];
#pragma unroll
    for (int i = 0; i < 8; ++i)
#pragma unroll
        for (int j = 0; j < 8; ++j) acc[i][j] = 0.f;

    for (int kc = 0; kc < ED; kc += 32) {
        __syncthreads();
        // stage enc tile [128t][32k] and Wenc tile transposed [32k][128a]
        for (int i = tid; i < 128 * 32; i += 256) {
            int r = i >> 5, k = i & 31;
            Es[r * 33 + k] = enc[(b * TT + t0 + r) * ED + kc + k];
            WsT[k * 136 + r] = Wenc[r * ED + kc + k];
        }
        __syncthreads();
#pragma unroll
        for (int k = 0; k < 32; ++k) {
            float er[8];
#pragma unroll
            for (int i = 0; i < 8; ++i) er[i] = Es[(ty * 8 + i) * 33 + k];
            float4 w0 = *(const float4*)&WsT[k * 136 + tx * 8];
            float4 w1 = *(const float4*)&WsT[k * 136 + tx * 8 + 4];
            float wr[8] = {w0.x, w0.y, w0.z, w0.w, w1.x, w1.y, w1.z, w1.w};
#pragma unroll
            for (int i = 0; i < 8; ++i)
#pragma unroll
                for (int j = 0; j < 8; ++j) acc[i][j] += er[i] * wr[j];
        }
    }

    // --- location-conv pass: acc[t][a] += sum_k M[a][k]*prev[t0+t+k-15]
    __syncthreads();
    for (int i = tid; i < AD * KS; i += 256) {
        int a = i / KS, k = i % KS;
        WsT[k * 136 + a] = g_M[i];   // reuse as M^T [k][a]
    }
    __syncthreads();
#pragma unroll
    for (int k = 0; k < KS; ++k) {
        float er[8];
#pragma unroll
        for (int i = 0; i < 8; ++i) er[i] = prev_s[ty * 8 + i + k];
        float4 w0 = *(const float4*)&WsT[k * 136 + tx * 8];
        float4 w1 = *(const float4*)&WsT[k * 136 + tx * 8 + 4];
        float wr[8] = {w0.x, w0.y, w0.z, w0.w, w1.x, w1.y, w1.z, w1.w};
#pragma unroll
        for (int i = 0; i < 8; ++i)
#pragma unroll
            for (int j = 0; j < 8; ++j) acc[i][j] += er[i] * wr[j];
    }

    // --- epilogue: energy[t] = sum_a vs[a]*tanh(acc + dec_proj[a]); reduce over tx
#pragma unroll
    for (int i = 0; i < 8; ++i) {
        float pe = 0.f;
#pragma unroll
        for (int j = 0; j < 8; ++j) {
            int a = tx * 8 + j;
            pe += vs[a] * tanhf(acc[i][j] + dps[a]);
        }
#pragma unroll
        for (int o = 8; o > 0; o >>= 1)
            pe += __shfl_down_sync(0xffffffffu, pe, o, 16);
        if (tx == 0) {
            int t = t0 + ty * 8 + i;
            float e = (mask[b * TT + t] == 0) ? -1e9f : pe;
            g_energy[b * TT + t] = e;
        }
    }
}

// ---------------------------------------------------------------------------
// Softmax over T per batch; writes attention weights into d_out[B*ED + ...]
__global__ __launch_bounds__(256) void k_softmax(float* __restrict__ out) {
    const int b = blockIdx.x;
    const int tid = threadIdx.x;
    __shared__ float red[8];

    float vals[8];
    float m = -1e30f;
#pragma unroll
    for (int i = 0; i < 8; ++i) {
        vals[i] = g_energy[b * TT + tid + i * 256];
        m = fmaxf(m, vals[i]);
    }
#pragma unroll
    for (int o = 16; o > 0; o >>= 1) m = fmaxf(m, __shfl_xor_sync(0xffffffffu, m, o));
    if ((tid & 31) == 0) red[tid >> 5] = m;
    __syncthreads();
    m = red[0];
#pragma unroll
    for (int w = 1; w < 8; ++w) m = fmaxf(m, red[w]);

    float s = 0.f;
#pragma unroll
    for (int i = 0; i < 8; ++i) {
        vals[i] = expf(vals[i] - m);
        s += vals[i];
    }
#pragma unroll
    for (int o = 16; o > 0; o >>= 1) s += __shfl_xor_sync(0xffffffffu, s, o);
    __syncthreads();
    if ((tid & 31) == 0) red[tid >> 5] = s;
    __syncthreads();
    s = 0.f;
#pragma unroll
    for (int w = 0; w < 8; ++w) s += red[w];

    float inv = 1.f / s;
    float* attn = out + BB * ED + b * TT;
#pragma unroll
    for (int i = 0; i < 8; ++i) attn[tid + i * 256] = vals[i] * inv;
}

// ---------------------------------------------------------------------------
// context[b][e] = sum_t attn[b][t]*enc[b][t][e]; split T into 8 chunks/batch.
__global__ __launch_bounds__(256) void k_context(const float* __restrict__ enc,
                                                 float* __restrict__ out) {
    const int b = blockIdx.y;
    const int tc = blockIdx.x;
    const int tid = threadIdx.x;
    __shared__ float ws[256];

    const float* attn = out + BB * ED + b * TT + tc * 256;
    ws[tid] = attn[tid];
    __syncthreads();

    float a0 = 0.f, a1 = 0.f;
    const float* e = enc + (size_t)(b * TT + tc * 256) * ED;
#pragma unroll 4
    for (int t = 0; t < 256; ++t) {
        float w = ws[t];
        a0 += w * e[(size_t)t * ED + tid];
        a1 += w * e[(size_t)t * ED + tid + 256];
    }
    atomicAdd(&out[b * ED + tid], a0);
    atomicAdd(&out[b * ED + tid + 256], a1);
}

// ---------------------------------------------------------------------------
extern "C" void kernel_launch(void* const* d_in, const int* in_sizes, int n_in,
                              void* d_out, int out_size) {
    const float* dec   = (const float*)d_in[0];  // [B, DD]
    const float* enc   = (const float*)d_in[1];  // [B, T, ED]
    const float* prev  = (const float*)d_in[2];  // [B, T]
    const int*   mask  = (const int*)d_in[3];    // [B, T]
    const float* convw = (const float*)d_in[4];  // [NF, 1, KS]
    const float* Wenc  = (const float*)d_in[5];  // [AD, ED]
    const float* Wdec  = (const float*)d_in[6];  // [AD, DD]
    const float* Wloc  = (const float*)d_in[7];  // [AD, NF]
    const float* v     = (const float*)d_in[8];  // [1, AD]
    float* out = (float*)d_out;                  // [B*ED context][B*T attn]

    k_prep_M<<<(AD * KS + 127) / 128, 128>>>(Wloc, convw);
    k_decproj<<<BB, AD>>>(Wdec, dec);
    k_zero<<<(BB * ED) / 256, 256>>>(out);
    dim3 eg(TT / 128, BB);
    k_energy<<<eg, 256>>>(enc, Wenc, prev, mask, v);
    k_softmax<<<BB, 256>>>(out);
    dim3 cg(8, BB);
    k_context<<<cg, 256>>>(enc, out);
}

// round 5
// speedup vs baseline: 1.3214x; 1.3214x over previous
#include <cuda_runtime.h>

#define BB 64
#define TT 2048
#define ED 512
#define DD 1024
#define AD 128
#define NF 32
#define KS 31
#define PADW 15

// scratch (no allocations allowed)
__device__ float g_M[AD * KS];        // folded conv*W_location  [a][k]
__device__ float g_dp[BB * AD];       // decoder projection      [b][a]
__device__ float g_energy[BB * TT];   // pre-softmax energies

#define FMA2(d, a, b) asm("fma.rn.f32x2 %0, %1, %2, %0;" : "+l"(d) : "l"(a), "l"(b))
#define PACK2(d, s)   asm("mov.b64 %0, {%1, %1};" : "=l"(d) : "f"(s))
#define UNPACK2(lo, hi, s) asm("mov.b64 {%0, %1}, %2;" : "=f"(lo), "=f"(hi) : "l"(s))

// ---------------------------------------------------------------------------
// Fold conv_w [F,1,KS] into W_location [A,F]:  M[a][k] = sum_f Wloc[a,f]*cw[f,k]
__global__ void k_prep_M(const float* __restrict__ Wloc,
                         const float* __restrict__ convw) {
    int idx = blockIdx.x * blockDim.x + threadIdx.x;
    if (idx < AD * KS) {
        int a = idx / KS, k = idx % KS;
        float s = 0.f;
#pragma unroll
        for (int f = 0; f < NF; ++f) s += Wloc[a * NF + f] * convw[f * KS + k];
        g_M[idx] = s;
    }
}

// ---------------------------------------------------------------------------
// dec_proj[b][a] = W_decoder[a,:] . decoder_state[b,:]
__global__ void k_decproj(const float* __restrict__ Wdec,
                          const float* __restrict__ dec) {
    int b = blockIdx.x;
    int a = threadIdx.x;
    const float* w = Wdec + a * DD;
    const float* x = dec + b * DD;
    float s = 0.f;
#pragma unroll 8
    for (int d = 0; d < DD; ++d) s += w[d] * x[d];
    g_dp[b * AD + a] = s;
}

// ---------------------------------------------------------------------------
__global__ void k_zero(float* __restrict__ out) {
    out[blockIdx.x * blockDim.x + threadIdx.x] = 0.f;
}

// ---------------------------------------------------------------------------
// Energy kernel: per block, 128 t-rows x 128 a-cols of enc_proj GEMM (f32x2
// packed FMA), plus folded location conv, then energy[t]=sum_a v[a]*tanh(...).
// Block: 256 threads = 16(tx: a-groups) x 16(ty: t-groups); 8x8 register tile
// held as 8x4 packed f32x2 accumulators (pairs along a).
__global__ __launch_bounds__(256) void k_energy(
    const float* __restrict__ enc, const float* __restrict__ Wenc,
    const float* __restrict__ prev, const int* __restrict__ mask,
    const float* __restrict__ v) {
    __shared__ __align__(16) float Es[128 * 33];   // [t][k] pad 33
    __shared__ __align__(16) float WsT[32 * 136];  // [k][a] pad 136 (reused for M^T)
    __shared__ float prev_s[160];
    __shared__ float dps[AD];
    __shared__ float vs[AD];

    const int tid = threadIdx.x;
    const int tx = tid & 15;         // a-group
    const int ty = tid >> 4;         // t-group
    const int b = blockIdx.y;
    const int t0 = blockIdx.x * 128;

    if (tid < AD) { dps[tid] = g_dp[b * AD + tid]; vs[tid] = v[tid]; }
    for (int i = tid; i < 158; i += 256) {
        int tg = t0 - PADW + i;
        prev_s[i] = (tg >= 0 && tg < TT) ? prev[b * TT + tg] : 0.f;
    }

    unsigned long long acc2[8][4];
#pragma unroll
    for (int i = 0; i < 8; ++i)
#pragma unroll
        for (int j = 0; j < 4; ++j) acc2[i][j] = 0ull;

    const int srow = tid >> 1;            // 0..127
    const int shalf = (tid & 1) * 16;     // 0 or 16

    for (int kc = 0; kc < ED; kc += 32) {
        __syncthreads();
        // stage enc tile [128t][32k] vectorized: thread -> row srow, cols shalf..shalf+15
        {
            const float4* src = (const float4*)&enc[(size_t)(b * TT + t0 + srow) * ED + kc + shalf];
#pragma unroll
            for (int c = 0; c < 4; ++c) {
                float4 x = src[c];
                float* dst = &Es[srow * 33 + shalf + c * 4];
                dst[0] = x.x; dst[1] = x.y; dst[2] = x.z; dst[3] = x.w;
            }
            // stage Wenc tile transposed [32k][128a]: row srow of Wenc, k-range shalf..+15
            const float4* ws = (const float4*)&Wenc[(size_t)srow * ED + kc + shalf];
#pragma unroll
            for (int c = 0; c < 4; ++c) {
                float4 x = ws[c];
                int kb = shalf + c * 4;
                WsT[(kb + 0) * 136 + srow] = x.x;
                WsT[(kb + 1) * 136 + srow] = x.y;
                WsT[(kb + 2) * 136 + srow] = x.z;
                WsT[(kb + 3) * 136 + srow] = x.w;
            }
        }
        __syncthreads();
#pragma unroll
        for (int k = 0; k < 32; ++k) {
            const ulonglong2* wp = (const ulonglong2*)&WsT[k * 136 + tx * 8];
            ulonglong2 wA = wp[0], wB = wp[1];
            unsigned long long w2[4] = {wA.x, wA.y, wB.x, wB.y};
#pragma unroll
            for (int i = 0; i < 8; ++i) {
                unsigned long long er2;
                PACK2(er2, Es[(ty * 8 + i) * 33 + k]);
#pragma unroll
                for (int j = 0; j < 4; ++j) FMA2(acc2[i][j], er2, w2[j]);
            }
        }
    }

    // --- location-conv pass: acc[t][a] += sum_k M[a][k]*prev[t0+t+k-15]
    __syncthreads();
    for (int i = tid; i < AD * KS; i += 256) {
        int a = i / KS, k = i % KS;
        WsT[k * 136 + a] = g_M[i];   // reuse as M^T [k][a]
    }
    __syncthreads();
#pragma unroll
    for (int k = 0; k < KS; ++k) {
        const ulonglong2* wp = (const ulonglong2*)&WsT[k * 136 + tx * 8];
        ulonglong2 wA = wp[0], wB = wp[1];
        unsigned long long w2[4] = {wA.x, wA.y, wB.x, wB.y};
#pragma unroll
        for (int i = 0; i < 8; ++i) {
            unsigned long long er2;
            PACK2(er2, prev_s[ty * 8 + i + k]);
#pragma unroll
            for (int j = 0; j < 4; ++j) FMA2(acc2[i][j], er2, w2[j]);
        }
    }

    // --- epilogue: energy[t] = sum_a vs[a]*tanh(acc + dec_proj[a]); reduce over tx
#pragma unroll
    for (int i = 0; i < 8; ++i) {
        float pe = 0.f;
#pragma unroll
        for (int j = 0; j < 4; ++j) {
            float lo, hi;
            UNPACK2(lo, hi, acc2[i][j]);
            int a = tx * 8 + 2 * j;
            pe += vs[a] * tanhf(lo + dps[a]);
            pe += vs[a + 1] * tanhf(hi + dps[a + 1]);
        }
#pragma unroll
        for (int o = 8; o > 0; o >>= 1)
            pe += __shfl_down_sync(0xffffffffu, pe, o, 16);
        if (tx == 0) {
            int t = t0 + ty * 8 + i;
            float e = (mask[b * TT + t] == 0) ? -1e9f : pe;
            g_energy[b * TT + t] = e;
        }
    }
}

// ---------------------------------------------------------------------------
// Softmax over T per batch; writes attention weights into d_out[B*ED + ...]
__global__ __launch_bounds__(256) void k_softmax(float* __restrict__ out) {
    const int b = blockIdx.x;
    const int tid = threadIdx.x;
    __shared__ float red[8];

    float vals[8];
    float m = -1e30f;
#pragma unroll
    for (int i = 0; i < 8; ++i) {
        vals[i] = g_energy[b * TT + tid + i * 256];
        m = fmaxf(m, vals[i]);
    }
#pragma unroll
    for (int o = 16; o > 0; o >>= 1) m = fmaxf(m, __shfl_xor_sync(0xffffffffu, m, o));
    if ((tid & 31) == 0) red[tid >> 5] = m;
    __syncthreads();
    m = red[0];
#pragma unroll
    for (int w = 1; w < 8; ++w) m = fmaxf(m, red[w]);

    float s = 0.f;
#pragma unroll
    for (int i = 0; i < 8; ++i) {
        vals[i] = expf(vals[i] - m);
        s += vals[i];
    }
#pragma unroll
    for (int o = 16; o > 0; o >>= 1) s += __shfl_xor_sync(0xffffffffu, s, o);
    __syncthreads();
    if ((tid & 31) == 0) red[tid >> 5] = s;
    __syncthreads();
    s = 0.f;
#pragma unroll
    for (int w = 0; w < 8; ++w) s += red[w];

    float inv = 1.f / s;
    float* attn = out + BB * ED + b * TT;
#pragma unroll
    for (int i = 0; i < 8; ++i) attn[tid + i * 256] = vals[i] * inv;
}

// ---------------------------------------------------------------------------
// context[b][e] = sum_t attn[b][t]*enc[b][t][e]; 16 t-chunks of 128 per batch.
// 128 threads; each thread owns a float4 column slice (tid*4).
__global__ __launch_bounds__(128) void k_context(const float* __restrict__ enc,
                                                 float* __restrict__ out) {
    const int b = blockIdx.y;
    const int tc = blockIdx.x;
    const int tid = threadIdx.x;
    __shared__ float ws[128];

    const float* attn = out + BB * ED + b * TT + tc * 128;
    if (tid < 128) ws[tid] = attn[tid];
    __syncthreads();

    float4 acc = make_float4(0.f, 0.f, 0.f, 0.f);
    const float* e = enc + (size_t)(b * TT + tc * 128) * ED + tid * 4;
#pragma unroll 4
    for (int t = 0; t < 128; ++t) {
        float w = ws[t];
        float4 x = *(const float4*)(e + (size_t)t * ED);
        acc.x += w * x.x; acc.y += w * x.y; acc.z += w * x.z; acc.w += w * x.w;
    }
    float* o = &out[b * ED + tid * 4];
    atomicAdd(o + 0, acc.x);
    atomicAdd(o + 1, acc.y);
    atomicAdd(o + 2, acc.z);
    atomicAdd(o + 3, acc.w);
}

// ---------------------------------------------------------------------------
extern "C" void kernel_launch(void* const* d_in, const int* in_sizes, int n_in,
                              void* d_out, int out_size) {
    const float* dec   = (const float*)d_in[0];  // [B, DD]
    const float* enc   = (const float*)d_in[1];  // [B, T, ED]
    const float* prev  = (const float*)d_in[2];  // [B, T]
    const int*   mask  = (const int*)d_in[3];    // [B, T]
    const float* convw = (const float*)d_in[4];  // [NF, 1, KS]
    const float* Wenc  = (const float*)d_in[5];  // [AD, ED]
    const float* Wdec  = (const float*)d_in[6];  // [AD, DD]
    const float* Wloc  = (const float*)d_in[7];  // [AD, NF]
    const float* v     = (const float*)d_in[8];  // [1, AD]
    float* out = (float*)d_out;                  // [B*ED context][B*T attn]

    k_prep_M<<<(AD * KS + 127) / 128, 128>>>(Wloc, convw);
    k_decproj<<<BB, AD>>>(Wdec, dec);
    k_zero<<<(BB * ED) / 256, 256>>>(out);
    dim3 eg(TT / 128, BB);
    k_energy<<<eg, 256>>>(enc, Wenc, prev, mask, v);
    k_softmax<<<BB, 256>>>(out);
    dim3 cg(16, BB);
    k_context<<<cg, 128>>>(enc, out);
}

// round 7
// speedup vs baseline: 2.0427x; 1.5458x over previous
#include <cuda_runtime.h>
#include <cuda_bf16.h>
#include <cstdint>

#define BB 64
#define TT 2048
#define ED 512
#define DD 1024
#define AD 128
#define NF 32
#define KS 31
#define PADW 15
#define NCHUNK 9       // 8 enc chunks of 64 + 1 folded chunk (31 conv + 1 dp + zeros)

// ---------------- scratch ----------------
__device__ float g_M[AD * KS];           // folded conv*W_location [a][k]
__device__ float g_dp[BB * AD];          // decoder projection [b][a]
__device__ float g_energy[BB * TT];      // pre-softmax energies
__device__ uint32_t g_Wh[8 * 128 * 32];  // Wenc bf16-hi [chunk][a][32 words]
__device__ uint32_t g_Wl[8 * 128 * 32];  // Wenc bf16-lo

// ---------------- helpers ----------------
__device__ __forceinline__ uint32_t smem_u32(const void* p) {
    uint32_t a;
    asm("{ .reg .u64 t; cvta.to.shared.u64 t, %1; cvt.u32.u64 %0, t; }" : "=r"(a) : "l"(p));
    return a;
}

// bf16 hi/lo split of float pair -> packed bf16x2 words (low half = x)
__device__ __forceinline__ void split2(float x, float y, uint32_t& h2, uint32_t& l2) {
    asm("cvt.rn.bf16x2.f32 %0, %1, %2;" : "=r"(h2) : "f"(y), "f"(x));
    __nv_bfloat162 hb = *reinterpret_cast<__nv_bfloat162*>(&h2);
    float rx = x - __bfloat162float(hb.x);
    float ry = y - __bfloat162float(hb.y);
    asm("cvt.rn.bf16x2.f32 %0, %1, %2;" : "=r"(l2) : "f"(ry), "f"(rx));
}

__device__ __forceinline__ void ldm_x4(uint32_t& r0, uint32_t& r1, uint32_t& r2,
                                       uint32_t& r3, uint32_t addr) {
    asm volatile("ldmatrix.sync.aligned.m8n8.x4.shared.b16 {%0,%1,%2,%3}, [%4];"
                 : "=r"(r0), "=r"(r1), "=r"(r2), "=r"(r3) : "r"(addr));
}

__device__ __forceinline__ void mma_bf16(float* d, const uint32_t* a,
                                         uint32_t b0, uint32_t b1) {
    asm volatile(
        "mma.sync.aligned.m16n8k16.row.col.f32.bf16.bf16.f32 "
        "{%0,%1,%2,%3}, {%4,%5,%6,%7}, {%8,%9}, {%0,%1,%2,%3};"
        : "+f"(d[0]), "+f"(d[1]), "+f"(d[2]), "+f"(d[3])
        : "r"(a[0]), "r"(a[1]), "r"(a[2]), "r"(a[3]), "r"(b0), "r"(b1));
}

// ---------------- smem layout (bytes); tile rows stride 72 bf16 = 144 B ----
#define STRB 144
#define S_AH 0
#define S_AL 18432
#define S_BH 36864
#define S_BL 55296
#define S_ES 73728            // 128 floats
#define S_VS 74240            // 128 floats
#define S_PR 74752            // 160 floats
#define SMEM_TC 75392

// ---------------------------------------------------------------------------
__global__ void k_prep_M(const float* __restrict__ Wloc,
                         const float* __restrict__ convw) {
    int idx = blockIdx.x * blockDim.x + threadIdx.x;
    if (idx < AD * KS) {
        int a = idx / KS, k = idx % KS;
        float s = 0.f;
#pragma unroll
        for (int f = 0; f < NF; ++f) s += Wloc[a * NF + f] * convw[f * KS + k];
        g_M[idx] = s;
    }
}

// ---------------------------------------------------------------------------
// Pre-split Wenc into bf16 hi/lo images, [chunk][a-row][64 k] (32 words/row).
__global__ void k_prep_Wimg(const float* __restrict__ Wenc) {
    int c = blockIdx.x;          // chunk 0..7
    int r = threadIdx.x;         // a-row 0..127
    const float4* src = (const float4*)(Wenc + (size_t)r * ED + c * 64);
    uint32_t* wh = g_Wh + (c * 128 + r) * 32;
    uint32_t* wl = g_Wl + (c * 128 + r) * 32;
#pragma unroll
    for (int p4 = 0; p4 < 16; ++p4) {
        float4 f = src[p4];
        uint32_t h0, l0, h1, l1;
        split2(f.x, f.y, h0, l0);
        split2(f.z, f.w, h1, l1);
        wh[p4 * 2] = h0; wh[p4 * 2 + 1] = h1;
        wl[p4 * 2] = l0; wl[p4 * 2 + 1] = l1;
    }
}

// ---------------------------------------------------------------------------
__global__ void k_decproj(const float* __restrict__ Wdec,
                          const float* __restrict__ dec) {
    int b = blockIdx.x;
    int a = threadIdx.x;
    const float* w = Wdec + a * DD;
    const float* x = dec + b * DD;
    float s = 0.f;
#pragma unroll 8
    for (int d = 0; d < DD; ++d) s += w[d] * x[d];
    g_dp[b * AD + a] = s;
}

// ---------------------------------------------------------------------------
__global__ void k_zero(float* __restrict__ out) {
    out[blockIdx.x * blockDim.x + threadIdx.x] = 0.f;
}

// ---------------------------------------------------------------------------
// Tensor-core energy kernel via mma.sync bf16 3-pass split.
// Block 256 thr / 8 warps; tile 128t x 128a; warp tile 32t x 64a.
// K = 576 (8*64 enc + 64 folded: 31 conv, 1 dp, zeros).
__global__ __launch_bounds__(256, 2) void k_energy_mma(
    const float* __restrict__ enc, const float* __restrict__ prev,
    const int* __restrict__ mask, const float* __restrict__ v) {
    extern __shared__ char smem[];
    const uint32_t sb = smem_u32(smem);
    const int tid = threadIdx.x;
    const int wid = tid >> 5;
    const int lane = tid & 31;
    const int warp_m = wid & 3;       // 32-row group
    const int warp_n = wid >> 2;      // 64-col group
    const int b = blockIdx.y;
    const int t0 = blockIdx.x * 128;

    float* e_s = (float*)(smem + S_ES);
    float* vs = (float*)(smem + S_VS);
    float* prev_s = (float*)(smem + S_PR);
    if (tid < 128) { e_s[tid] = 0.f; vs[tid] = v[tid]; }
    for (int i = tid; i < 158; i += 256) {
        int tg = t0 - PADW + i;
        prev_s[i] = (tg >= 0 && tg < TT) ? prev[b * TT + tg] : 0.f;
    }

    float acc[2][8][4];
#pragma unroll
    for (int mt = 0; mt < 2; ++mt)
#pragma unroll
        for (int nt = 0; nt < 8; ++nt)
#pragma unroll
            for (int q = 0; q < 4; ++q) acc[mt][nt][q] = 0.f;

    const int row = tid >> 1;        // staging row 0..127
    const int half = tid & 1;        // staging col half (32 elems)

    for (int c = 0; c < NCHUNK; ++c) {
        __syncthreads();
        if (c < 8) {
            // A: enc rows -> bf16 hi/lo
            const float4* src =
                (const float4*)(enc + ((size_t)(b * TT + t0 + row)) * ED + c * 64 + half * 32);
            char* ah = smem + S_AH + row * STRB + half * 64;
            char* al = smem + S_AL + row * STRB + half * 64;
#pragma unroll
            for (int p4 = 0; p4 < 8; ++p4) {
                float4 f = src[p4];
                uint32_t h0, l0, h1, l1;
                split2(f.x, f.y, h0, l0);
                split2(f.z, f.w, h1, l1);
                ((uint32_t*)(ah + p4 * 8))[0] = h0;
                ((uint32_t*)(ah + p4 * 8))[1] = h1;
                ((uint32_t*)(al + p4 * 8))[0] = l0;
                ((uint32_t*)(al + p4 * 8))[1] = l1;
            }
            // B: copy pre-split Wenc images
            const uint4* sh = (const uint4*)(g_Wh + (c * 128 + row) * 32 + half * 16);
            const uint4* sl = (const uint4*)(g_Wl + (c * 128 + row) * 32 + half * 16);
            uint4* bh = (uint4*)(smem + S_BH + row * STRB + half * 64);
            uint4* bl = (uint4*)(smem + S_BL + row * STRB + half * 64);
#pragma unroll
            for (int q = 0; q < 4; ++q) { bh[q] = sh[q]; bl[q] = sl[q]; }
        } else {
            // folded chunk: cols 0..30 conv taps, col 31 = (1.0, dp), cols 32+ zero
            char* ah = smem + S_AH + row * STRB + half * 64;
            char* al = smem + S_AL + row * STRB + half * 64;
            char* bh = smem + S_BH + row * STRB + half * 64;
            char* bl = smem + S_BL + row * STRB + half * 64;
            if (half == 0) {
                float dpv = g_dp[b * AD + row];
#pragma unroll
                for (int p = 0; p < 16; ++p) {
                    int j0 = 2 * p, j1 = 2 * p + 1;
                    float ax = prev_s[row + j0];
                    float bx = g_M[row * KS + j0];
                    float ay = (j1 < 31) ? prev_s[row + j1] : 1.f;
                    float by = (j1 < 31) ? g_M[row * KS + j1] : dpv;
                    uint32_t h, l;
                    split2(ax, ay, h, l);
                    ((uint32_t*)(ah + p * 4))[0] = h;
                    ((uint32_t*)(al + p * 4))[0] = l;
                    split2(bx, by, h, l);
                    ((uint32_t*)(bh + p * 4))[0] = h;
                    ((uint32_t*)(bl + p * 4))[0] = l;
                }
            } else {
#pragma unroll
                for (int p = 0; p < 4; ++p) {
                    ((uint4*)ah)[p] = make_uint4(0, 0, 0, 0);
                    ((uint4*)al)[p] = make_uint4(0, 0, 0, 0);
                    ((uint4*)bh)[p] = make_uint4(0, 0, 0, 0);
                    ((uint4*)bl)[p] = make_uint4(0, 0, 0, 0);
                }
            }
        }
        __syncthreads();

#pragma unroll
        for (int kk = 0; kk < 4; ++kk) {
            uint32_t bh[16], bl[16];
#pragma unroll
            for (int g = 0; g < 4; ++g) {
                uint32_t roff = (uint32_t)((warp_n * 64 + g * 16 + (lane & 15)) * STRB +
                                           kk * 32 + (lane >> 4) * 16);
                ldm_x4(bh[g * 4], bh[g * 4 + 1], bh[g * 4 + 2], bh[g * 4 + 3],
                       sb + S_BH + roff);
                ldm_x4(bl[g * 4], bl[g * 4 + 1], bl[g * 4 + 2], bl[g * 4 + 3],
                       sb + S_BL + roff);
            }
#pragma unroll
            for (int mt = 0; mt < 2; ++mt) {
                uint32_t ah[4], al[4];
                uint32_t aoff = (uint32_t)((warp_m * 32 + mt * 16 + (lane & 15)) * STRB +
                                           kk * 32 + (lane >> 4) * 16);
                ldm_x4(ah[0], ah[1], ah[2], ah[3], sb + S_AH + aoff);
                ldm_x4(al[0], al[1], al[2], al[3], sb + S_AL + aoff);
#pragma unroll
                for (int g = 0; g < 4; ++g) {
                    // n-tiles 2g (regs {0,2}) and 2g+1 (regs {1,3})
                    mma_bf16(acc[mt][2 * g],     ah, bh[g * 4],     bh[g * 4 + 2]);
                    mma_bf16(acc[mt][2 * g + 1], ah, bh[g * 4 + 1], bh[g * 4 + 3]);
                    mma_bf16(acc[mt][2 * g],     ah, bl[g * 4],     bl[g * 4 + 2]);
                    mma_bf16(acc[mt][2 * g + 1], ah, bl[g * 4 + 1], bl[g * 4 + 3]);
                    mma_bf16(acc[mt][2 * g],     al, bh[g * 4],     bh[g * 4 + 2]);
                    mma_bf16(acc[mt][2 * g + 1], al, bh[g * 4 + 1], bh[g * 4 + 3]);
                }
            }
        }
    }

    // ---- epilogue: energy[t] = sum_a v[a]*tanh(D[t][a]) (dp/conv already in D)
#pragma unroll
    for (int mt = 0; mt < 2; ++mt) {
        float p0 = 0.f, p8 = 0.f;
#pragma unroll
        for (int nt = 0; nt < 8; ++nt) {
            int a0 = warp_n * 64 + nt * 8 + (lane & 3) * 2;
            p0 += vs[a0] * tanhf(acc[mt][nt][0]) + vs[a0 + 1] * tanhf(acc[mt][nt][1]);
            p8 += vs[a0] * tanhf(acc[mt][nt][2]) + vs[a0 + 1] * tanhf(acc[mt][nt][3]);
        }
        p0 += __shfl_xor_sync(0xffffffffu, p0, 1);
        p0 += __shfl_xor_sync(0xffffffffu, p0, 2);
        p8 += __shfl_xor_sync(0xffffffffu, p8, 1);
        p8 += __shfl_xor_sync(0xffffffffu, p8, 2);
        if ((lane & 3) == 0) {
            int rbase = warp_m * 32 + mt * 16 + (lane >> 2);
            atomicAdd(&e_s[rbase], p0);
            atomicAdd(&e_s[rbase + 8], p8);
        }
    }
    __syncthreads();
    if (tid < 128) {
        int t = t0 + tid;
        float e = (mask[b * TT + t] == 0) ? -1e9f : e_s[tid];
        g_energy[b * TT + t] = e;
    }
}

// ---------------------------------------------------------------------------
__global__ __launch_bounds__(256) void k_softmax(float* __restrict__ out) {
    const int b = blockIdx.x;
    const int tid = threadIdx.x;
    __shared__ float red[8];

    float vals[8];
    float m = -1e30f;
#pragma unroll
    for (int i = 0; i < 8; ++i) {
        vals[i] = g_energy[b * TT + tid + i * 256];
        m = fmaxf(m, vals[i]);
    }
#pragma unroll
    for (int o = 16; o > 0; o >>= 1) m = fmaxf(m, __shfl_xor_sync(0xffffffffu, m, o));
    if ((tid & 31) == 0) red[tid >> 5] = m;
    __syncthreads();
    m = red[0];
#pragma unroll
    for (int w = 1; w < 8; ++w) m = fmaxf(m, red[w]);

    float s = 0.f;
#pragma unroll
    for (int i = 0; i < 8; ++i) {
        vals[i] = expf(vals[i] - m);
        s += vals[i];
    }
#pragma unroll
    for (int o = 16; o > 0; o >>= 1) s += __shfl_xor_sync(0xffffffffu, s, o);
    __syncthreads();
    if ((tid & 31) == 0) red[tid >> 5] = s;
    __syncthreads();
    s = 0.f;
#pragma unroll
    for (int w = 0; w < 8; ++w) s += red[w];

    float inv = 1.f / s;
    float* attn = out + BB * ED + b * TT;
#pragma unroll
    for (int i = 0; i < 8; ++i) attn[tid + i * 256] = vals[i] * inv;
}

// ---------------------------------------------------------------------------
__global__ __launch_bounds__(128) void k_context(const float* __restrict__ enc,
                                                 float* __restrict__ out) {
    const int b = blockIdx.y;
    const int tc = blockIdx.x;
    const int tid = threadIdx.x;
    __shared__ float ws[128];

    const float* attn = out + BB * ED + b * TT + tc * 128;
    ws[tid] = attn[tid];
    __syncthreads();

    float4 acc = make_float4(0.f, 0.f, 0.f, 0.f);
    const float* e = enc + (size_t)(b * TT + tc * 128) * ED + tid * 4;
#pragma unroll 4
    for (int t = 0; t < 128; ++t) {
        float w = ws[t];
        float4 x = *(const float4*)(e + (size_t)t * ED);
        acc.x += w * x.x; acc.y += w * x.y; acc.z += w * x.z; acc.w += w * x.w;
    }
    float* o = &out[b * ED + tid * 4];
    atomicAdd(o + 0, acc.x);
    atomicAdd(o + 1, acc.y);
    atomicAdd(o + 2, acc.z);
    atomicAdd(o + 3, acc.w);
}

// ---------------------------------------------------------------------------
extern "C" void kernel_launch(void* const* d_in, const int* in_sizes, int n_in,
                              void* d_out, int out_size) {
    const float* dec   = (const float*)d_in[0];
    const float* enc   = (const float*)d_in[1];
    const float* prev  = (const float*)d_in[2];
    const int*   mask  = (const int*)d_in[3];
    const float* convw = (const float*)d_in[4];
    const float* Wenc  = (const float*)d_in[5];
    const float* Wdec  = (const float*)d_in[6];
    const float* Wloc  = (const float*)d_in[7];
    const float* v     = (const float*)d_in[8];
    float* out = (float*)d_out;

    cudaFuncSetAttribute(k_energy_mma, cudaFuncAttributeMaxDynamicSharedMemorySize, SMEM_TC);

    k_prep_M<<<(AD * KS + 127) / 128, 128>>>(Wloc, convw);
    k_prep_Wimg<<<8, 128>>>(Wenc);
    k_decproj<<<BB, AD>>>(Wdec, dec);
    k_zero<<<(BB * ED) / 256, 256>>>(out);
    dim3 eg(TT / 128, BB);
    k_energy_mma<<<eg, 256, SMEM_TC>>>(enc, prev, mask, v);
    k_softmax<<<BB, 256>>>(out);
    dim3 cg(16, BB);
    k_context<<<cg, 128>>>(enc, out);
}

// round 8
// speedup vs baseline: 2.3667x; 1.1586x over previous
#include <cuda_runtime.h>
#include <cuda_fp16.h>
#include <cstdint>

#define BB 64
#define TT 2048
#define ED 512
#define DD 1024
#define AD 128
#define NF 32
#define KS 31
#define PADW 15
#define NCHUNK 9       // 8 enc chunks of 64 + 1 folded conv chunk

// ---------------- scratch ----------------
__device__ float g_M[AD * KS];           // folded conv*W_location [a][k]
__device__ float g_dp[BB * AD];          // decoder projection [b][a]
__device__ float g_energy[BB * TT];      // pre-softmax energies
__device__ uint32_t g_Wh[9 * 128 * 32];  // B fp16-hi images [chunk][a][32 words]
__device__ uint32_t g_Wl[9 * 128 * 32];  // B fp16-lo images

// ---------------- helpers ----------------
__device__ __forceinline__ uint32_t smem_u32(const void* p) {
    uint32_t a;
    asm("{ .reg .u64 t; cvta.to.shared.u64 t, %1; cvt.u32.u64 %0, t; }" : "=r"(a) : "l"(p));
    return a;
}

__device__ __forceinline__ uint32_t packh(float x, float y) {
    __half2 h = __floats2half2_rn(x, y);      // .x = x (low half)
    return *reinterpret_cast<uint32_t*>(&h);
}

// fp16 hi/lo split of a float pair -> packed half2 words (low half = x)
__device__ __forceinline__ void splith(float x, float y, uint32_t& h2, uint32_t& l2) {
    __half2 hb = __floats2half2_rn(x, y);
    h2 = *reinterpret_cast<uint32_t*>(&hb);
    float rx = x - __half2float(__low2half(hb));
    float ry = y - __half2float(__high2half(hb));
    __half2 lb = __floats2half2_rn(rx, ry);
    l2 = *reinterpret_cast<uint32_t*>(&lb);
}

__device__ __forceinline__ void ldm_x4(uint32_t& r0, uint32_t& r1, uint32_t& r2,
                                       uint32_t& r3, uint32_t addr) {
    asm volatile("ldmatrix.sync.aligned.m8n8.x4.shared.b16 {%0,%1,%2,%3}, [%4];"
                 : "=r"(r0), "=r"(r1), "=r"(r2), "=r"(r3) : "r"(addr));
}

__device__ __forceinline__ void mma_f16(float* d, const uint32_t* a,
                                        uint32_t b0, uint32_t b1) {
    asm volatile(
        "mma.sync.aligned.m16n8k16.row.col.f32.f16.f16.f32 "
        "{%0,%1,%2,%3}, {%4,%5,%6,%7}, {%8,%9}, {%0,%1,%2,%3};"
        : "+f"(d[0]), "+f"(d[1]), "+f"(d[2]), "+f"(d[3])
        : "r"(a[0]), "r"(a[1]), "r"(a[2]), "r"(a[3]), "r"(b0), "r"(b1));
}

#define CPA16(dst, src) \
    asm volatile("cp.async.cg.shared.global [%0], [%1], 16;" :: "r"(dst), "l"(src))
#define CP_COMMIT() asm volatile("cp.async.commit_group;" ::: "memory")
#define CP_WAIT1()  asm volatile("cp.async.wait_group 1;" ::: "memory")

// ---------------- smem layout (bytes); row stride 144 B ----------------
#define STRB 144
#define S_AH 0                         // 18432
#define S_B  18432                     // 2 bufs x (BH 18432 + BL 18432)
#define S_ES 92160                     // 128 floats
#define S_VS 92672                     // 128 floats
#define S_DP 93184                     // 128 floats
#define S_PR 93696                     // 160 floats
#define SMEM_TC 94336

// ---------------------------------------------------------------------------
__global__ void k_prep_M(const float* __restrict__ Wloc,
                         const float* __restrict__ convw) {
    int idx = blockIdx.x * blockDim.x + threadIdx.x;
    if (idx < AD * KS) {
        int a = idx / KS, k = idx % KS;
        float s = 0.f;
#pragma unroll
        for (int f = 0; f < NF; ++f) s += Wloc[a * NF + f] * convw[f * KS + k];
        g_M[idx] = s;
    }
}

// ---------------------------------------------------------------------------
// B images: chunks 0..7 = Wenc fp16 hi/lo split; chunk 8 = folded conv M
// (cols 0..30 = M[a][k], cols 31..63 = 0). dp is added in the epilogue.
__global__ void k_prep_Wimg(const float* __restrict__ Wenc) {
    int c = blockIdx.x;          // chunk 0..8
    int r = threadIdx.x;         // a-row 0..127
    uint32_t* wh = g_Wh + (c * 128 + r) * 32;
    uint32_t* wl = g_Wl + (c * 128 + r) * 32;
    if (c < 8) {
        const float4* src = (const float4*)(Wenc + (size_t)r * ED + c * 64);
#pragma unroll
        for (int p4 = 0; p4 < 16; ++p4) {
            float4 f = src[p4];
            uint32_t h0, l0, h1, l1;
            splith(f.x, f.y, h0, l0);
            splith(f.z, f.w, h1, l1);
            wh[p4 * 2] = h0; wh[p4 * 2 + 1] = h1;
            wl[p4 * 2] = l0; wl[p4 * 2 + 1] = l1;
        }
    } else {
#pragma unroll
        for (int p = 0; p < 32; ++p) {
            int j0 = 2 * p, j1 = 2 * p + 1;
            float x = (j0 < KS) ? g_M[r * KS + j0] : 0.f;
            float y = (j1 < KS) ? g_M[r * KS + j1] : 0.f;
            uint32_t h, l;
            splith(x, y, h, l);
            wh[p] = h; wl[p] = l;
        }
    }
}

// ---------------------------------------------------------------------------
__global__ void k_decproj(const float* __restrict__ Wdec,
                          const float* __restrict__ dec) {
    int b = blockIdx.x;
    int a = threadIdx.x;
    const float* w = Wdec + a * DD;
    const float* x = dec + b * DD;
    float s = 0.f;
#pragma unroll 8
    for (int d = 0; d < DD; ++d) s += w[d] * x[d];
    g_dp[b * AD + a] = s;
}

// ---------------------------------------------------------------------------
__global__ void k_zero(float* __restrict__ out) {
    out[blockIdx.x * blockDim.x + threadIdx.x] = 0.f;
}

// ---------------------------------------------------------------------------
// Energy kernel: fp16 asymmetric split (A=enc rounded; B=Wenc hi+lo), 2 MMA
// passes, cp.async double-buffered B, dp added in fp32 epilogue.
// Block 256 thr / 8 warps; tile 128t x 128a; warp tile 32t x 64a; K=576.
__global__ __launch_bounds__(256, 2) void k_energy_mma(
    const float* __restrict__ enc, const float* __restrict__ prev,
    const int* __restrict__ mask, const float* __restrict__ v) {
    extern __shared__ char smem[];
    const uint32_t sb = smem_u32(smem);
    const int tid = threadIdx.x;
    const int wid = tid >> 5;
    const int lane = tid & 31;
    const int warp_m = wid & 3;
    const int warp_n = wid >> 2;
    const int b = blockIdx.y;
    const int t0 = blockIdx.x * 128;

    float* e_s = (float*)(smem + S_ES);
    float* vs = (float*)(smem + S_VS);
    float* dps = (float*)(smem + S_DP);
    float* prev_s = (float*)(smem + S_PR);
    if (tid < 128) {
        e_s[tid] = 0.f;
        vs[tid] = v[tid];
        dps[tid] = g_dp[b * AD + tid];
    }
    for (int i = tid; i < 158; i += 256) {
        int tg = t0 - PADW + i;
        prev_s[i] = (tg >= 0 && tg < TT) ? prev[b * TT + tg] : 0.f;
    }

    float acc[2][8][4];
#pragma unroll
    for (int mt = 0; mt < 2; ++mt)
#pragma unroll
        for (int nt = 0; nt < 8; ++nt)
#pragma unroll
            for (int q = 0; q < 4; ++q) acc[mt][nt][q] = 0.f;

    const int row = tid >> 1;
    const int half = tid & 1;

    // prologue: prefetch B chunk 0 into buf 0
    {
        const char* sh = (const char*)(g_Wh + (0 * 128 + row) * 32) + half * 64;
        const char* sl = (const char*)(g_Wl + (0 * 128 + row) * 32) + half * 64;
        uint32_t dh = sb + S_B + row * STRB + half * 64;
        uint32_t dl = dh + 18432;
#pragma unroll
        for (int q = 0; q < 4; ++q) {
            CPA16(dh + q * 16, sh + q * 16);
            CPA16(dl + q * 16, sl + q * 16);
        }
        CP_COMMIT();
    }

    for (int c = 0; c < NCHUNK; ++c) {
        __syncthreads();   // prior compute done reading AH / B[(c-1)&1]

        // stage A chunk c (fp16 rounded)
        uint32_t* ah = (uint32_t*)(smem + S_AH + row * STRB + half * 64);
        if (c < 8) {
            const float4* src =
                (const float4*)(enc + ((size_t)(b * TT + t0 + row)) * ED + c * 64 + half * 32);
#pragma unroll
            for (int p4 = 0; p4 < 8; ++p4) {
                float4 f = src[p4];
                ah[p4 * 2] = packh(f.x, f.y);
                ah[p4 * 2 + 1] = packh(f.z, f.w);
            }
        } else {
            if (half == 0) {
#pragma unroll
                for (int p = 0; p < 16; ++p) {
                    int j0 = 2 * p, j1 = 2 * p + 1;
                    float x = (j0 < KS) ? prev_s[row + j0] : 0.f;
                    float y = (j1 < KS) ? prev_s[row + j1] : 0.f;
                    ah[p] = packh(x, y);
                }
            } else {
#pragma unroll
                for (int p = 0; p < 4; ++p) ((uint4*)ah)[p] = make_uint4(0, 0, 0, 0);
            }
        }

        // prefetch B chunk c+1 into buf (c+1)&1
        if (c + 1 < NCHUNK) {
            int nb = (c + 1) & 1;
            const char* sh = (const char*)(g_Wh + ((c + 1) * 128 + row) * 32) + half * 64;
            const char* sl = (const char*)(g_Wl + ((c + 1) * 128 + row) * 32) + half * 64;
            uint32_t dh = sb + S_B + nb * 36864 + row * STRB + half * 64;
            uint32_t dl = dh + 18432;
#pragma unroll
            for (int q = 0; q < 4; ++q) {
                CPA16(dh + q * 16, sh + q * 16);
                CPA16(dl + q * 16, sl + q * 16);
            }
        }
        CP_COMMIT();
        CP_WAIT1();        // B chunk c complete
        __syncthreads();

        const uint32_t bufH = sb + S_B + (c & 1) * 36864;
        const uint32_t bufL = bufH + 18432;

#pragma unroll
        for (int kk = 0; kk < 4; ++kk) {
            uint32_t ah0[4], ah1[4];
            uint32_t aoff = (uint32_t)((warp_m * 32 + (lane & 15)) * STRB +
                                       kk * 32 + (lane >> 4) * 16);
            ldm_x4(ah0[0], ah0[1], ah0[2], ah0[3], sb + S_AH + aoff);
            ldm_x4(ah1[0], ah1[1], ah1[2], ah1[3], sb + S_AH + aoff + 16 * STRB);
#pragma unroll
            for (int g = 0; g < 4; ++g) {
                uint32_t roff = (uint32_t)((warp_n * 64 + g * 16 + (lane & 15)) * STRB +
                                           kk * 32 + (lane >> 4) * 16);
                uint32_t b0, b1, b2, b3;
                ldm_x4(b0, b1, b2, b3, bufH + roff);
                mma_f16(acc[0][2 * g],     ah0, b0, b2);
                mma_f16(acc[0][2 * g + 1], ah0, b1, b3);
                mma_f16(acc[1][2 * g],     ah1, b0, b2);
                mma_f16(acc[1][2 * g + 1], ah1, b1, b3);
                ldm_x4(b0, b1, b2, b3, bufL + roff);
                mma_f16(acc[0][2 * g],     ah0, b0, b2);
                mma_f16(acc[0][2 * g + 1], ah0, b1, b3);
                mma_f16(acc[1][2 * g],     ah1, b0, b2);
                mma_f16(acc[1][2 * g + 1], ah1, b1, b3);
            }
        }
    }

    // ---- epilogue: energy[t] = sum_a v[a]*tanh(D[t][a] + dp[a])
#pragma unroll
    for (int mt = 0; mt < 2; ++mt) {
        float p0 = 0.f, p8 = 0.f;
#pragma unroll
        for (int nt = 0; nt < 8; ++nt) {
            int a0 = warp_n * 64 + nt * 8 + (lane & 3) * 2;
            p0 += vs[a0] * tanhf(acc[mt][nt][0] + dps[a0]) +
                  vs[a0 + 1] * tanhf(acc[mt][nt][1] + dps[a0 + 1]);
            p8 += vs[a0] * tanhf(acc[mt][nt][2] + dps[a0]) +
                  vs[a0 + 1] * tanhf(acc[mt][nt][3] + dps[a0 + 1]);
        }
        p0 += __shfl_xor_sync(0xffffffffu, p0, 1);
        p0 += __shfl_xor_sync(0xffffffffu, p0, 2);
        p8 += __shfl_xor_sync(0xffffffffu, p8, 1);
        p8 += __shfl_xor_sync(0xffffffffu, p8, 2);
        if ((lane & 3) == 0) {
            int rbase = warp_m * 32 + mt * 16 + (lane >> 2);
            atomicAdd(&e_s[rbase], p0);
            atomicAdd(&e_s[rbase + 8], p8);
        }
    }
    __syncthreads();
    if (tid < 128) {
        int t = t0 + tid;
        float e = (mask[b * TT + t] == 0) ? -1e9f : e_s[tid];
        g_energy[b * TT + t] = e;
    }
}

// ---------------------------------------------------------------------------
__global__ __launch_bounds__(256) void k_softmax(float* __restrict__ out) {
    const int b = blockIdx.x;
    const int tid = threadIdx.x;
    __shared__ float red[8];

    float vals[8];
    float m = -1e30f;
#pragma unroll
    for (int i = 0; i < 8; ++i) {
        vals[i] = g_energy[b * TT + tid + i * 256];
        m = fmaxf(m, vals[i]);
    }
#pragma unroll
    for (int o = 16; o > 0; o >>= 1) m = fmaxf(m, __shfl_xor_sync(0xffffffffu, m, o));
    if ((tid & 31) == 0) red[tid >> 5] = m;
    __syncthreads();
    m = red[0];
#pragma unroll
    for (int w = 1; w < 8; ++w) m = fmaxf(m, red[w]);

    float s = 0.f;
#pragma unroll
    for (int i = 0; i < 8; ++i) {
        vals[i] = expf(vals[i] - m);
        s += vals[i];
    }
#pragma unroll
    for (int o = 16; o > 0; o >>= 1) s += __shfl_xor_sync(0xffffffffu, s, o);
    __syncthreads();
    if ((tid & 31) == 0) red[tid >> 5] = s;
    __syncthreads();
    s = 0.f;
#pragma unroll
    for (int w = 0; w < 8; ++w) s += red[w];

    float inv = 1.f / s;
    float* attn = out + BB * ED + b * TT;
#pragma unroll
    for (int i = 0; i < 8; ++i) attn[tid + i * 256] = vals[i] * inv;
}

// ---------------------------------------------------------------------------
__global__ __launch_bounds__(128) void k_context(const float* __restrict__ enc,
                                                 float* __restrict__ out) {
    const int b = blockIdx.y;
    const int tc = blockIdx.x;
    const int tid = threadIdx.x;
    __shared__ float ws[128];

    const float* attn = out + BB * ED + b * TT + tc * 128;
    ws[tid] = attn[tid];
    __syncthreads();

    float4 acc = make_float4(0.f, 0.f, 0.f, 0.f);
    const float* e = enc + (size_t)(b * TT + tc * 128) * ED + tid * 4;
#pragma unroll 4
    for (int t = 0; t < 128; ++t) {
        float w = ws[t];
        float4 x = *(const float4*)(e + (size_t)t * ED);
        acc.x += w * x.x; acc.y += w * x.y; acc.z += w * x.z; acc.w += w * x.w;
    }
    float* o = &out[b * ED + tid * 4];
    atomicAdd(o + 0, acc.x);
    atomicAdd(o + 1, acc.y);
    atomicAdd(o + 2, acc.z);
    atomicAdd(o + 3, acc.w);
}

// ---------------------------------------------------------------------------
extern "C" void kernel_launch(void* const* d_in, const int* in_sizes, int n_in,
                              void* d_out, int out_size) {
    const float* dec   = (const float*)d_in[0];
    const float* enc   = (const float*)d_in[1];
    const float* prev  = (const float*)d_in[2];
    const int*   mask  = (const int*)d_in[3];
    const float* convw = (const float*)d_in[4];
    const float* Wenc  = (const float*)d_in[5];
    const float* Wdec  = (const float*)d_in[6];
    const float* Wloc  = (const float*)d_in[7];
    const float* v     = (const float*)d_in[8];
    float* out = (float*)d_out;

    cudaFuncSetAttribute(k_energy_mma, cudaFuncAttributeMaxDynamicSharedMemorySize, SMEM_TC);

    k_prep_M<<<(AD * KS + 127) / 128, 128>>>(Wloc, convw);
    k_prep_Wimg<<<9, 128>>>(Wenc);
    k_decproj<<<BB, AD>>>(Wdec, dec);
    k_zero<<<(BB * ED) / 256, 256>>>(out);
    dim3 eg(TT / 128, BB);
    k_energy_mma<<<eg, 256, SMEM_TC>>>(enc, prev, mask, v);
    k_softmax<<<BB, 256>>>(out);
    dim3 cg(16, BB);
    k_context<<<cg, 128>>>(enc, out);
}